// round 15
// baseline (speedup 1.0000x reference)
#include <cuda_runtime.h>
#include <cuda_fp16.h>
#include <math.h>

constexpr int FIN = 256;
constexpr int HC1 = 32;    // heads1 * out_ch1 = 2*16
constexpr int C2  = 40;
constexpr int NMAX = 100000;
constexpr int ETMAX = 3400000;   // E + N self loops
#define NEG 0.2f

// ---------------- scratch (device globals) ----------------
__device__ __align__(16) __half g_h1h[NMAX * HC1];   // fp16 h1 (layer-1 gather payload)
__device__ __align__(16) float g_asrc1[NMAX * 2];
__device__ __align__(16) float g_adst1[NMAX * 2];
__device__ __align__(16) __half g_rh[NMAX * HC1];    // fp16 r = relu(agg+b1) (layer-2 payload)
__device__ float g_asrc2[NMAX];
__device__ float g_adst2[NMAX];
__device__ float g_was[HC1];     // W2 @ att_src2
__device__ float g_wad[HC1];     // W2 @ att_dst2
__device__ int g_deg[NMAX];      // zero-initialized; re-zeroed by k_scan1 each replay
__device__ int g_rowstart[NMAX + 1];
__device__ int g_cursor[NMAX];
__device__ int g_adj[ETMAX];
// decoupled-lookback scan state (reset by k_hist each replay)
__device__ int g_scan_flag[128];
__device__ int g_scan_agg[128];
__device__ int g_scan_pref[128];

__device__ __forceinline__ unsigned f2tf32(float f) {
    unsigned r;
    asm("cvt.rna.tf32.f32 %0, %1;" : "=r"(r) : "f"(f));
    return r;
}
__device__ __forceinline__ void mma_tf32(float* d, unsigned a0, unsigned a1,
                                         unsigned a2, unsigned a3,
                                         unsigned b0, unsigned b1) {
    asm("mma.sync.aligned.m16n8k8.row.col.f32.tf32.tf32.f32 "
        "{%0,%1,%2,%3},{%4,%5,%6,%7},{%8,%9},{%0,%1,%2,%3};"
        : "+f"(d[0]), "+f"(d[1]), "+f"(d[2]), "+f"(d[3])
        : "r"(a0), "r"(a1), "r"(a2), "r"(a3), "r"(b0), "r"(b1));
}

// ---------------------------------------------------------------------------
// K1: h1 = x @ W1 via tf32 tensor-core mma (m16n8k8). (measured 51us)
// ---------------------------------------------------------------------------
__global__ __launch_bounds__(256, 4) void k1_gemm(
    const float* __restrict__ x, const float* __restrict__ W1,
    const float* __restrict__ as1v, const float* __restrict__ ad1v, int N) {
    __shared__ unsigned xs[128 * 36];   // tf32 bits, [row][k]
    __shared__ unsigned ws[32 * 40];    // tf32 bits, [k][n]
    int tid = threadIdx.x;
    int warp = tid >> 5, lane = tid & 31;
    int g = lane >> 2, tg = lane & 3;
    int node0 = blockIdx.x * 128;
    int r0 = warp * 16;

    float d[4][4];
    #pragma unroll
    for (int nb = 0; nb < 4; nb++)
        #pragma unroll
        for (int q = 0; q < 4; q++) d[nb][q] = 0.f;

    for (int kc = 0; kc < 8; kc++) {
        __syncthreads();
        #pragma unroll
        for (int i = 0; i < 4; i++) {
            int idx = tid + i * 256;
            int k = idx >> 5, n = idx & 31;
            ws[k * 40 + n] = f2tf32(W1[(kc * 32 + k) * HC1 + n]);
        }
        #pragma unroll
        for (int i = 0; i < 4; i++) {
            int idx = tid + i * 256;
            int rr = idx >> 3, cg = (idx & 7) * 4;
            int gr = node0 + rr;
            float4 v = (gr < N) ? *(const float4*)&x[(long long)gr * FIN + kc * 32 + cg]
                                : make_float4(0.f, 0.f, 0.f, 0.f);
            unsigned* p = &xs[rr * 36 + cg];
            p[0] = f2tf32(v.x); p[1] = f2tf32(v.y);
            p[2] = f2tf32(v.z); p[3] = f2tf32(v.w);
        }
        __syncthreads();
        #pragma unroll
        for (int ks = 0; ks < 4; ks++) {
            int kb = ks * 8;
            unsigned a0 = xs[(r0 + g) * 36 + kb + tg];
            unsigned a1 = xs[(r0 + g + 8) * 36 + kb + tg];
            unsigned a2 = xs[(r0 + g) * 36 + kb + tg + 4];
            unsigned a3 = xs[(r0 + g + 8) * 36 + kb + tg + 4];
            #pragma unroll
            for (int nb = 0; nb < 4; nb++) {
                unsigned b0 = ws[(kb + tg) * 40 + nb * 8 + g];
                unsigned b1 = ws[(kb + tg + 4) * 40 + nb * 8 + g];
                mma_tf32(d[nb], a0, a1, a2, a3, b0, b1);
            }
        }
    }

    int ra = node0 + r0 + g;
    int rb = ra + 8;
    float as_[4][2], ad_[4][2];
    #pragma unroll
    for (int nb = 0; nb < 4; nb++) {
        int c = nb * 8 + 2 * tg;
        as_[nb][0] = __ldg(&as1v[c]);     as_[nb][1] = __ldg(&as1v[c + 1]);
        ad_[nb][0] = __ldg(&ad1v[c]);     ad_[nb][1] = __ldg(&ad1v[c + 1]);
    }
    float psA[2] = {0.f, 0.f}, pdA[2] = {0.f, 0.f};
    float psB[2] = {0.f, 0.f}, pdB[2] = {0.f, 0.f};
    #pragma unroll
    for (int nb = 0; nb < 4; nb++) {
        int h = nb >> 1;
        psA[h] += d[nb][0] * as_[nb][0] + d[nb][1] * as_[nb][1];
        pdA[h] += d[nb][0] * ad_[nb][0] + d[nb][1] * ad_[nb][1];
        psB[h] += d[nb][2] * as_[nb][0] + d[nb][3] * as_[nb][1];
        pdB[h] += d[nb][2] * ad_[nb][0] + d[nb][3] * ad_[nb][1];
    }
    #pragma unroll
    for (int h = 0; h < 2; h++) {
        psA[h] += __shfl_xor_sync(0xffffffffu, psA[h], 1);
        psA[h] += __shfl_xor_sync(0xffffffffu, psA[h], 2);
        pdA[h] += __shfl_xor_sync(0xffffffffu, pdA[h], 1);
        pdA[h] += __shfl_xor_sync(0xffffffffu, pdA[h], 2);
        psB[h] += __shfl_xor_sync(0xffffffffu, psB[h], 1);
        psB[h] += __shfl_xor_sync(0xffffffffu, psB[h], 2);
        pdB[h] += __shfl_xor_sync(0xffffffffu, pdB[h], 1);
        pdB[h] += __shfl_xor_sync(0xffffffffu, pdB[h], 2);
    }
    if (ra < N) {
        #pragma unroll
        for (int nb = 0; nb < 4; nb++) {
            __half2 h2 = __floats2half2_rn(d[nb][0], d[nb][1]);
            *(__half2*)&g_h1h[ra * HC1 + nb * 8 + 2 * tg] = h2;
        }
        if (tg == 0) {
            g_asrc1[2 * ra] = psA[0]; g_asrc1[2 * ra + 1] = psA[1];
            g_adst1[2 * ra] = pdA[0]; g_adst1[2 * ra + 1] = pdA[1];
        }
    }
    if (rb < N) {
        #pragma unroll
        for (int nb = 0; nb < 4; nb++) {
            __half2 h2 = __floats2half2_rn(d[nb][2], d[nb][3]);
            *(__half2*)&g_h1h[rb * HC1 + nb * 8 + 2 * tg] = h2;
        }
        if (tg == 0) {
            g_asrc1[2 * rb] = psB[0]; g_asrc1[2 * rb + 1] = psB[1];
            g_adst1[2 * rb] = pdB[0]; g_adst1[2 * rb + 1] = pdB[1];
        }
    }
}

// ---------------------------------------------------------------------------
// CSR build (RED hist, lookback scan, atomic fill)
// ---------------------------------------------------------------------------
__global__ void k_hist(const int* __restrict__ ei, int E, int vec) {
    int gid = blockIdx.x * blockDim.x + threadIdx.x;
    if (gid < 128) g_scan_flag[gid] = 0;
    int e4 = gid * 4;
    if (e4 >= E) return;
    if (vec && e4 + 4 <= E) {
        int4 d = *(const int4*)&ei[E + e4];
        atomicAdd(&g_deg[d.x], 1);
        atomicAdd(&g_deg[d.y], 1);
        atomicAdd(&g_deg[d.z], 1);
        atomicAdd(&g_deg[d.w], 1);
    } else {
        for (int e = e4; e < E && e < e4 + 4; e++) atomicAdd(&g_deg[ei[E + e]], 1);
    }
}

__global__ __launch_bounds__(1024) void k_scan1(int N) {
    __shared__ int wsum[32];
    __shared__ int s_total;
    __shared__ int s_exc;
    int tid = threadIdx.x, lane = tid & 31, warp = tid >> 5;
    int bid = blockIdx.x;
    int idx = bid * 1024 + tid;

    int v = 0;
    if (idx < N) { v = g_deg[idx] + 1; g_deg[idx] = 0; }

    int sv = v;
    #pragma unroll
    for (int o = 1; o < 32; o <<= 1) {
        int t = __shfl_up_sync(0xffffffffu, sv, o);
        if (lane >= o) sv += t;
    }
    if (lane == 31) wsum[warp] = sv;
    __syncthreads();
    if (warp == 0) {
        int w = wsum[lane];
        int sw = w;
        #pragma unroll
        for (int o = 1; o < 32; o <<= 1) {
            int t = __shfl_up_sync(0xffffffffu, sw, o);
            if (lane >= o) sw += t;
        }
        wsum[lane] = sw - w;
        if (lane == 31) s_total = sw;
    }
    __syncthreads();
    int incl = sv + wsum[warp];
    int total = s_total;

    if (tid == 0) {
        if (bid == 0) {
            g_scan_pref[0] = total;
            __threadfence();
            g_scan_flag[0] = 2;
            s_exc = 0;
        } else {
            g_scan_agg[bid] = total;
            __threadfence();
            g_scan_flag[bid] = 1;
            int exc = 0;
            for (int j = bid - 1;;) {
                int f;
                do { f = *(volatile int*)&g_scan_flag[j]; } while (f == 0);
                __threadfence();
                if (f == 2) { exc += *(volatile int*)&g_scan_pref[j]; break; }
                exc += *(volatile int*)&g_scan_agg[j];
                j--;
            }
            g_scan_pref[bid] = exc + total;
            __threadfence();
            g_scan_flag[bid] = 2;
            s_exc = exc;
        }
    }
    __syncthreads();
    int base = s_exc;
    if (idx < N) {
        int rs = base + incl - v;
        g_rowstart[idx] = rs;
        g_adj[rs] = idx;            // self loop first
        g_cursor[idx] = rs + 1;
        if (idx == N - 1) g_rowstart[N] = base + incl;
    }
}

__global__ void k_fill(const int* __restrict__ ei, int E, int vec) {
    int gid = blockIdx.x * blockDim.x + threadIdx.x;
    int e4 = gid * 4;
    if (e4 >= E) return;
    if (vec && e4 + 4 <= E) {
        int4 s = *(const int4*)&ei[e4];
        int4 d = *(const int4*)&ei[E + e4];
        g_adj[atomicAdd(&g_cursor[d.x], 1)] = s.x;
        g_adj[atomicAdd(&g_cursor[d.y], 1)] = s.y;
        g_adj[atomicAdd(&g_cursor[d.z], 1)] = s.z;
        g_adj[atomicAdd(&g_cursor[d.w], 1)] = s.w;
    } else {
        for (int e = e4; e < E && e < e4 + 4; e++)
            g_adj[atomicAdd(&g_cursor[ei[E + e]], 1)] = ei[e];
    }
}

// k_watt: was = W2 @ as2, wad = W2 @ ad2 (32 each). Tiny.
__global__ void k_watt(const float* __restrict__ W2,
                       const float* __restrict__ as2, const float* __restrict__ ad2) {
    int k = threadIdx.x;
    if (k < HC1) {
        float s = 0.f, d = 0.f;
        #pragma unroll
        for (int c = 0; c < C2; c++) {
            float w = W2[k * C2 + c];
            s += w * as2[c];
            d += w * ad2[c];
        }
        g_was[k] = s;
        g_wad[k] = d;
    }
}

// ---------------------------------------------------------------------------
// K2: layer-1 aggregation (2 neighbors/iter, half2/lane). Epilogue emits
// r = relu(agg+b1) as fp16 (layer-2 payload) and the layer-2 logits via
// precomputed was/wad.
// ---------------------------------------------------------------------------
__global__ __launch_bounds__(256) void k2_gather(const float* __restrict__ b1, int N) {
    __shared__ unsigned soff[8][32];    // byte offset of neighbor's h1 row
    __shared__ float se[8][2][32];      // [head][slot] exp weights
    int warp = threadIdx.x >> 5, lane = threadIdx.x & 31;
    int n = blockIdx.x * 8 + warp;
    if (n >= N) return;
    int lh = lane & 15;        // channel pair index: channels 2lh, 2lh+1
    int hh = lane >> 4;        // neighbor parity this lane sweeps
    int ehsel = lh >> 3;       // head of this lane's channels
    float2 adst = *(const float2*)&g_adst1[2 * n];
    int start = g_rowstart[n], end = g_rowstart[n + 1];
    float2 acc = make_float2(0.f, 0.f);
    float evs0 = 0.f, evs1 = 0.f;
    const char* hbase = (const char*)g_h1h + 4 * lh;

    for (int i = start; i < end; i += 32) {
        int idx = i + lane;
        bool valid = idx < end;
        int s = valid ? g_adj[idx] : 0;
        float2 l = valid ? *(const float2*)&g_asrc1[2 * s] : make_float2(0.f, 0.f);
        float a0 = l.x + adst.x; a0 = (a0 > 0.f) ? a0 : NEG * a0;
        float a1 = l.y + adst.y; a1 = (a1 > 0.f) ? a1 : NEG * a1;
        float e0 = valid ? __expf(a0) : 0.f;
        float e1 = valid ? __expf(a1) : 0.f;
        evs0 += e0; evs1 += e1;
        soff[warp][lane] = (unsigned)s * (HC1 * 2);
        se[warp][0][lane] = e0;
        se[warp][1][lane] = e1;
        __syncwarp();
        int cnt = min(32, end - i);
        #pragma unroll 4
        for (int j = 0; j < cnt; j += 2) {
            int jj = j + hh;
            unsigned offB = soff[warp][jj];
            float eh = se[warp][ehsel][jj];
            __half2 hv = *(const __half2*)(hbase + offB);
            float2 fv = __half22float2(hv);
            acc.x += eh * fv.x;
            acc.y += eh * fv.y;
        }
        __syncwarp();
    }
    acc.x += __shfl_xor_sync(0xffffffffu, acc.x, 16);
    acc.y += __shfl_xor_sync(0xffffffffu, acc.y, 16);
    #pragma unroll
    for (int o = 16; o >= 1; o >>= 1) {
        evs0 += __shfl_xor_sync(0xffffffffu, evs0, o);
        evs1 += __shfl_xor_sync(0xffffffffu, evs1, o);
    }
    float evs = (ehsel == 0) ? evs0 : evs1;
    float inv = 1.f / (evs + 1e-16f);
    float r0 = fmaxf(acc.x * inv + __ldg(&b1[2 * lh]), 0.f);
    float r1 = fmaxf(acc.y * inv + __ldg(&b1[2 * lh + 1]), 0.f);
    float s2 = r0 * g_was[2 * lh] + r1 * g_was[2 * lh + 1];
    float d2 = r0 * g_wad[2 * lh] + r1 * g_wad[2 * lh + 1];
    #pragma unroll
    for (int o = 8; o >= 1; o >>= 1) {
        s2 += __shfl_xor_sync(0xffffffffu, s2, o);
        d2 += __shfl_xor_sync(0xffffffffu, d2, o);
    }
    if (lane == 0) { g_asrc2[n] = s2; g_adst2[n] = d2; }
    if (lane < 16) {
        __half2 rp = __floats2half2_rn(r0, r1);
        *(__half2*)&g_rh[n * HC1 + 2 * lh] = rp;
    }
}

// ---------------------------------------------------------------------------
// K45: layer-2 aggregation of r + FUSED W2 GEMV + log_softmax output.
// Gather phase identical to the R14 k4; epilogue does the 32x40 GEMV from
// per-warp smem aggregate + W2 staged in shared, then log_softmax in-warp.
// ---------------------------------------------------------------------------
__global__ __launch_bounds__(256) void k45_gather_out(
    const float* __restrict__ W2, const float* __restrict__ b2,
    float* __restrict__ out, int N) {
    __shared__ unsigned soff[8][32];
    __shared__ float se[8][32];
    __shared__ float ragg[8][32];
    __shared__ float w2s[HC1 * C2];   // 5KB
    __shared__ float b2s[C2];
    int tid = threadIdx.x;
    for (int i = tid; i < HC1 * C2; i += 256) w2s[i] = W2[i];
    if (tid < C2) b2s[tid] = b2[tid];
    __syncthreads();

    int warp = tid >> 5, lane = tid & 31;
    int n = blockIdx.x * 8 + warp;
    if (n >= N) return;
    int lh = lane & 15;
    int hh = lane >> 4;
    float adstv = g_adst2[n];
    int start = g_rowstart[n], end = g_rowstart[n + 1];
    float2 acc = make_float2(0.f, 0.f);
    float evs = 0.f;
    const char* hbase = (const char*)g_rh + 4 * lh;

    for (int i = start; i < end; i += 32) {
        int idx = i + lane;
        bool valid = idx < end;
        int s = valid ? g_adj[idx] : 0;
        float l = valid ? g_asrc2[s] : 0.f;
        float a = l + adstv; a = (a > 0.f) ? a : NEG * a;
        float e = valid ? __expf(a) : 0.f;
        evs += e;
        soff[warp][lane] = (unsigned)s * (HC1 * 2);
        se[warp][lane] = e;
        __syncwarp();
        int cnt = min(32, end - i);
        #pragma unroll 4
        for (int j = 0; j < cnt; j += 2) {
            int jj = j + hh;
            unsigned offB = soff[warp][jj];
            float eh = se[warp][jj];
            __half2 hv = *(const __half2*)(hbase + offB);
            float2 fv = __half22float2(hv);
            acc.x += eh * fv.x;
            acc.y += eh * fv.y;
        }
        __syncwarp();
    }
    acc.x += __shfl_xor_sync(0xffffffffu, acc.x, 16);
    acc.y += __shfl_xor_sync(0xffffffffu, acc.y, 16);
    #pragma unroll
    for (int o = 16; o >= 1; o >>= 1) evs += __shfl_xor_sync(0xffffffffu, evs, o);
    float inv = 1.f / (evs + 1e-16f);
    if (lane < 16) {
        ragg[warp][2 * lh]     = acc.x * inv;
        ragg[warp][2 * lh + 1] = acc.y * inv;
    }
    __syncwarp();

    // fused GEMV: lanes 0..19 compute output channels 2*lane, 2*lane+1
    bool act = lane < 20;
    int c0 = 2 * lane;
    float o0 = 0.f, o1 = 0.f;
    if (act) {
        #pragma unroll
        for (int k = 0; k < HC1; k++) {
            float rv = ragg[warp][k];
            float2 w = *(const float2*)&w2s[k * C2 + c0];
            o0 += rv * w.x;
            o1 += rv * w.y;
        }
        o0 += b2s[c0];
        o1 += b2s[c0 + 1];
    }
    float v0 = act ? o0 : -INFINITY;
    float v1 = act ? o1 : -INFINITY;
    float m = fmaxf(v0, v1);
    #pragma unroll
    for (int o = 16; o >= 1; o >>= 1) m = fmaxf(m, __shfl_xor_sync(0xffffffffu, m, o));
    float ssum = act ? (__expf(v0 - m) + __expf(v1 - m)) : 0.f;
    #pragma unroll
    for (int o = 16; o >= 1; o >>= 1) ssum += __shfl_xor_sync(0xffffffffu, ssum, o);
    float lse = m + __logf(ssum);
    if (act) {
        *(float2*)&out[n * C2 + c0] = make_float2(v0 - lse, v1 - lse);
    }
}

// ---------------------------------------------------------------------------
extern "C" void kernel_launch(void* const* d_in, const int* in_sizes, int n_in,
                              void* d_out, int out_size) {
    const float* x   = (const float*)d_in[0];
    const int*   ei  = (const int*)d_in[1];
    const float* W1  = (const float*)d_in[2];
    const float* as1 = (const float*)d_in[3];
    const float* ad1 = (const float*)d_in[4];
    const float* b1  = (const float*)d_in[5];
    const float* W2  = (const float*)d_in[6];
    const float* as2 = (const float*)d_in[7];
    const float* ad2 = (const float*)d_in[8];
    const float* b2  = (const float*)d_in[9];
    float* out = (float*)d_out;

    int N  = in_sizes[0] / FIN;
    int E  = in_sizes[1] / 2;
    int vec = ((E & 3) == 0) ? 1 : 0;
    int eThreads = (E + 3) / 4;
    int scanBlocks = (N + 1023) / 1024;   // <= 128

    static cudaStream_t sB = nullptr;
    static cudaEvent_t evF = nullptr, evJ = nullptr;
    if (sB == nullptr) {
        cudaStreamCreateWithFlags(&sB, cudaStreamNonBlocking);
        cudaEventCreateWithFlags(&evF, cudaEventDisableTiming);
        cudaEventCreateWithFlags(&evJ, cudaEventDisableTiming);
    }

    // Fork: CSR build + watt on sB alongside k1 GEMM on the main stream.
    cudaEventRecord(evF, 0);
    cudaStreamWaitEvent(sB, evF, 0);

    k_hist<<<(eThreads + 255) / 256, 256, 0, sB>>>(ei, E, vec);
    k_scan1<<<scanBlocks, 1024, 0, sB>>>(N);
    k_fill<<<(eThreads + 255) / 256, 256, 0, sB>>>(ei, E, vec);
    k1_gemm<<<(N + 127) / 128, 256>>>(x, W1, as1, ad1, N);    // main stream (4th launch)
    k_watt<<<1, 32, 0, sB>>>(W2, as2, ad2);

    // Join.
    cudaEventRecord(evJ, sB);
    cudaStreamWaitEvent(0, evJ, 0);

    k2_gather<<<(N + 7) / 8, 256>>>(b1, N);
    k45_gather_out<<<(N + 7) / 8, 256>>>(W2, b2, out, N);
}

// round 16
// speedup vs baseline: 1.0695x; 1.0695x over previous
#include <cuda_runtime.h>
#include <cuda_fp16.h>
#include <math.h>

constexpr int FIN = 256;
constexpr int HC1 = 32;    // heads1 * out_ch1 = 2*16
constexpr int C2  = 40;
constexpr int NMAX = 100000;
constexpr int ETMAX = 3400000;   // E + N self loops
#define NEG 0.2f

// ---------------- scratch (device globals) ----------------
__device__ __align__(16) __half g_h1h[NMAX * HC1];   // fp16 h1 (layer-1 gather payload)
__device__ __align__(16) float g_asrc1[NMAX * 2];
__device__ __align__(16) float g_adst1[NMAX * 2];
__device__ __align__(16) __half g_rh[NMAX * HC1];    // fp16 r = relu(agg+b1) (layer-2 payload)
__device__ __align__(16) float g_agg[NMAX * HC1];    // layer-2 aggregated r (fp32)
__device__ float g_asrc2[NMAX];
__device__ float g_adst2[NMAX];
__device__ float g_was[HC1];     // W2 @ att_src2
__device__ float g_wad[HC1];     // W2 @ att_dst2
__device__ int g_deg[NMAX];      // zero-initialized; re-zeroed by k_scan1 each replay
__device__ int g_rowstart[NMAX + 1];
__device__ int g_cursor[NMAX];
__device__ int g_adj[ETMAX];
// decoupled-lookback scan state (reset by k_hist each replay)
__device__ int g_scan_flag[128];
__device__ int g_scan_agg[128];
__device__ int g_scan_pref[128];

__device__ __forceinline__ unsigned f2tf32(float f) {
    unsigned r;
    asm("cvt.rna.tf32.f32 %0, %1;" : "=r"(r) : "f"(f));
    return r;
}
__device__ __forceinline__ void mma_tf32(float* d, unsigned a0, unsigned a1,
                                         unsigned a2, unsigned a3,
                                         unsigned b0, unsigned b1) {
    asm("mma.sync.aligned.m16n8k8.row.col.f32.tf32.tf32.f32 "
        "{%0,%1,%2,%3},{%4,%5,%6,%7},{%8,%9},{%0,%1,%2,%3};"
        : "+f"(d[0]), "+f"(d[1]), "+f"(d[2]), "+f"(d[3])
        : "r"(a0), "r"(a1), "r"(a2), "r"(a3), "r"(b0), "r"(b1));
}

// ---------------------------------------------------------------------------
// K1: h1 = x @ W1 via tf32 tensor-core mma (m16n8k8). (measured 51us)
// ---------------------------------------------------------------------------
__global__ __launch_bounds__(256, 4) void k1_gemm(
    const float* __restrict__ x, const float* __restrict__ W1,
    const float* __restrict__ as1v, const float* __restrict__ ad1v, int N) {
    __shared__ unsigned xs[128 * 36];   // tf32 bits, [row][k]
    __shared__ unsigned ws[32 * 40];    // tf32 bits, [k][n]
    int tid = threadIdx.x;
    int warp = tid >> 5, lane = tid & 31;
    int g = lane >> 2, tg = lane & 3;
    int node0 = blockIdx.x * 128;
    int r0 = warp * 16;

    float d[4][4];
    #pragma unroll
    for (int nb = 0; nb < 4; nb++)
        #pragma unroll
        for (int q = 0; q < 4; q++) d[nb][q] = 0.f;

    for (int kc = 0; kc < 8; kc++) {
        __syncthreads();
        #pragma unroll
        for (int i = 0; i < 4; i++) {
            int idx = tid + i * 256;
            int k = idx >> 5, n = idx & 31;
            ws[k * 40 + n] = f2tf32(W1[(kc * 32 + k) * HC1 + n]);
        }
        #pragma unroll
        for (int i = 0; i < 4; i++) {
            int idx = tid + i * 256;
            int rr = idx >> 3, cg = (idx & 7) * 4;
            int gr = node0 + rr;
            float4 v = (gr < N) ? *(const float4*)&x[(long long)gr * FIN + kc * 32 + cg]
                                : make_float4(0.f, 0.f, 0.f, 0.f);
            unsigned* p = &xs[rr * 36 + cg];
            p[0] = f2tf32(v.x); p[1] = f2tf32(v.y);
            p[2] = f2tf32(v.z); p[3] = f2tf32(v.w);
        }
        __syncthreads();
        #pragma unroll
        for (int ks = 0; ks < 4; ks++) {
            int kb = ks * 8;
            unsigned a0 = xs[(r0 + g) * 36 + kb + tg];
            unsigned a1 = xs[(r0 + g + 8) * 36 + kb + tg];
            unsigned a2 = xs[(r0 + g) * 36 + kb + tg + 4];
            unsigned a3 = xs[(r0 + g + 8) * 36 + kb + tg + 4];
            #pragma unroll
            for (int nb = 0; nb < 4; nb++) {
                unsigned b0 = ws[(kb + tg) * 40 + nb * 8 + g];
                unsigned b1 = ws[(kb + tg + 4) * 40 + nb * 8 + g];
                mma_tf32(d[nb], a0, a1, a2, a3, b0, b1);
            }
        }
    }

    int ra = node0 + r0 + g;
    int rb = ra + 8;
    float as_[4][2], ad_[4][2];
    #pragma unroll
    for (int nb = 0; nb < 4; nb++) {
        int c = nb * 8 + 2 * tg;
        as_[nb][0] = __ldg(&as1v[c]);     as_[nb][1] = __ldg(&as1v[c + 1]);
        ad_[nb][0] = __ldg(&ad1v[c]);     ad_[nb][1] = __ldg(&ad1v[c + 1]);
    }
    float psA[2] = {0.f, 0.f}, pdA[2] = {0.f, 0.f};
    float psB[2] = {0.f, 0.f}, pdB[2] = {0.f, 0.f};
    #pragma unroll
    for (int nb = 0; nb < 4; nb++) {
        int h = nb >> 1;
        psA[h] += d[nb][0] * as_[nb][0] + d[nb][1] * as_[nb][1];
        pdA[h] += d[nb][0] * ad_[nb][0] + d[nb][1] * ad_[nb][1];
        psB[h] += d[nb][2] * as_[nb][0] + d[nb][3] * as_[nb][1];
        pdB[h] += d[nb][2] * ad_[nb][0] + d[nb][3] * ad_[nb][1];
    }
    #pragma unroll
    for (int h = 0; h < 2; h++) {
        psA[h] += __shfl_xor_sync(0xffffffffu, psA[h], 1);
        psA[h] += __shfl_xor_sync(0xffffffffu, psA[h], 2);
        pdA[h] += __shfl_xor_sync(0xffffffffu, pdA[h], 1);
        pdA[h] += __shfl_xor_sync(0xffffffffu, pdA[h], 2);
        psB[h] += __shfl_xor_sync(0xffffffffu, psB[h], 1);
        psB[h] += __shfl_xor_sync(0xffffffffu, psB[h], 2);
        pdB[h] += __shfl_xor_sync(0xffffffffu, pdB[h], 1);
        pdB[h] += __shfl_xor_sync(0xffffffffu, pdB[h], 2);
    }
    if (ra < N) {
        #pragma unroll
        for (int nb = 0; nb < 4; nb++) {
            __half2 h2 = __floats2half2_rn(d[nb][0], d[nb][1]);
            *(__half2*)&g_h1h[ra * HC1 + nb * 8 + 2 * tg] = h2;
        }
        if (tg == 0) {
            g_asrc1[2 * ra] = psA[0]; g_asrc1[2 * ra + 1] = psA[1];
            g_adst1[2 * ra] = pdA[0]; g_adst1[2 * ra + 1] = pdA[1];
        }
    }
    if (rb < N) {
        #pragma unroll
        for (int nb = 0; nb < 4; nb++) {
            __half2 h2 = __floats2half2_rn(d[nb][2], d[nb][3]);
            *(__half2*)&g_h1h[rb * HC1 + nb * 8 + 2 * tg] = h2;
        }
        if (tg == 0) {
            g_asrc1[2 * rb] = psB[0]; g_asrc1[2 * rb + 1] = psB[1];
            g_adst1[2 * rb] = pdB[0]; g_adst1[2 * rb + 1] = pdB[1];
        }
    }
}

// ---------------------------------------------------------------------------
// CSR build (RED hist, lookback scan, atomic fill)
// ---------------------------------------------------------------------------
__global__ void k_hist(const int* __restrict__ ei, int E, int vec) {
    int gid = blockIdx.x * blockDim.x + threadIdx.x;
    if (gid < 128) g_scan_flag[gid] = 0;
    int e4 = gid * 4;
    if (e4 >= E) return;
    if (vec && e4 + 4 <= E) {
        int4 d = *(const int4*)&ei[E + e4];
        atomicAdd(&g_deg[d.x], 1);
        atomicAdd(&g_deg[d.y], 1);
        atomicAdd(&g_deg[d.z], 1);
        atomicAdd(&g_deg[d.w], 1);
    } else {
        for (int e = e4; e < E && e < e4 + 4; e++) atomicAdd(&g_deg[ei[E + e]], 1);
    }
}

__global__ __launch_bounds__(1024) void k_scan1(int N) {
    __shared__ int wsum[32];
    __shared__ int s_total;
    __shared__ int s_exc;
    int tid = threadIdx.x, lane = tid & 31, warp = tid >> 5;
    int bid = blockIdx.x;
    int idx = bid * 1024 + tid;

    int v = 0;
    if (idx < N) { v = g_deg[idx] + 1; g_deg[idx] = 0; }

    int sv = v;
    #pragma unroll
    for (int o = 1; o < 32; o <<= 1) {
        int t = __shfl_up_sync(0xffffffffu, sv, o);
        if (lane >= o) sv += t;
    }
    if (lane == 31) wsum[warp] = sv;
    __syncthreads();
    if (warp == 0) {
        int w = wsum[lane];
        int sw = w;
        #pragma unroll
        for (int o = 1; o < 32; o <<= 1) {
            int t = __shfl_up_sync(0xffffffffu, sw, o);
            if (lane >= o) sw += t;
        }
        wsum[lane] = sw - w;
        if (lane == 31) s_total = sw;
    }
    __syncthreads();
    int incl = sv + wsum[warp];
    int total = s_total;

    if (tid == 0) {
        if (bid == 0) {
            g_scan_pref[0] = total;
            __threadfence();
            g_scan_flag[0] = 2;
            s_exc = 0;
        } else {
            g_scan_agg[bid] = total;
            __threadfence();
            g_scan_flag[bid] = 1;
            int exc = 0;
            for (int j = bid - 1;;) {
                int f;
                do { f = *(volatile int*)&g_scan_flag[j]; } while (f == 0);
                __threadfence();
                if (f == 2) { exc += *(volatile int*)&g_scan_pref[j]; break; }
                exc += *(volatile int*)&g_scan_agg[j];
                j--;
            }
            g_scan_pref[bid] = exc + total;
            __threadfence();
            g_scan_flag[bid] = 2;
            s_exc = exc;
        }
    }
    __syncthreads();
    int base = s_exc;
    if (idx < N) {
        int rs = base + incl - v;
        g_rowstart[idx] = rs;
        g_adj[rs] = idx;            // self loop first
        g_cursor[idx] = rs + 1;
        if (idx == N - 1) g_rowstart[N] = base + incl;
    }
}

__global__ void k_fill(const int* __restrict__ ei, int E, int vec) {
    int gid = blockIdx.x * blockDim.x + threadIdx.x;
    int e4 = gid * 4;
    if (e4 >= E) return;
    if (vec && e4 + 4 <= E) {
        int4 s = *(const int4*)&ei[e4];
        int4 d = *(const int4*)&ei[E + e4];
        g_adj[atomicAdd(&g_cursor[d.x], 1)] = s.x;
        g_adj[atomicAdd(&g_cursor[d.y], 1)] = s.y;
        g_adj[atomicAdd(&g_cursor[d.z], 1)] = s.z;
        g_adj[atomicAdd(&g_cursor[d.w], 1)] = s.w;
    } else {
        for (int e = e4; e < E && e < e4 + 4; e++)
            g_adj[atomicAdd(&g_cursor[ei[E + e]], 1)] = ei[e];
    }
}

// k_watt: was = W2 @ as2, wad = W2 @ ad2 (32 each). Tiny.
__global__ void k_watt(const float* __restrict__ W2,
                       const float* __restrict__ as2, const float* __restrict__ ad2) {
    int k = threadIdx.x;
    if (k < HC1) {
        float s = 0.f, d = 0.f;
        #pragma unroll
        for (int c = 0; c < C2; c++) {
            float w = W2[k * C2 + c];
            s += w * as2[c];
            d += w * ad2[c];
        }
        g_was[k] = s;
        g_wad[k] = d;
    }
}

// ---------------------------------------------------------------------------
// K2: layer-1 aggregation, SOFTWARE-PIPELINED chunks: next chunk's adj +
// logits prefetched into registers before sweeping the current chunk, so the
// sweep covers the prefetch's L2 latency. Epilogue emits fp16 r + layer-2
// logits via precomputed was/wad.
// ---------------------------------------------------------------------------
__global__ __launch_bounds__(256) void k2_gather(const float* __restrict__ b1, int N) {
    __shared__ unsigned soff[8][32];
    __shared__ float se[8][2][32];
    int warp = threadIdx.x >> 5, lane = threadIdx.x & 31;
    int n = blockIdx.x * 8 + warp;
    if (n >= N) return;
    int lh = lane & 15;
    int hh = lane >> 4;
    int ehsel = lh >> 3;
    float2 adst = *(const float2*)&g_adst1[2 * n];
    int start = g_rowstart[n], end = g_rowstart[n + 1];
    float2 acc = make_float2(0.f, 0.f);
    float evs0 = 0.f, evs1 = 0.f;
    const char* hbase = (const char*)g_h1h + 4 * lh;

    // prologue prefetch of chunk 0
    int i = start;
    int idx0 = i + lane;
    bool v0 = idx0 < end;
    int s = v0 ? g_adj[idx0] : 0;
    float2 l = v0 ? *(const float2*)&g_asrc1[2 * s] : make_float2(-1e30f, -1e30f);

    while (i < end) {
        // exp for current chunk (invalid lanes carry l=-1e30 -> exp ~ 0)
        float a0 = l.x + adst.x; a0 = (a0 > 0.f) ? a0 : NEG * a0;
        float a1 = l.y + adst.y; a1 = (a1 > 0.f) ? a1 : NEG * a1;
        float e0 = __expf(a0);
        float e1 = __expf(a1);
        evs0 += e0; evs1 += e1;
        soff[warp][lane] = (unsigned)s * (HC1 * 2);
        se[warp][0][lane] = e0;
        se[warp][1][lane] = e1;
        __syncwarp();
        // prefetch next chunk before the sweep
        int inext = i + 32;
        int s_n = 0;
        float2 l_n = make_float2(-1e30f, -1e30f);
        if (inext < end) {
            int idxn = inext + lane;
            bool vn = idxn < end;
            s_n = vn ? g_adj[idxn] : 0;
            if (vn) l_n = *(const float2*)&g_asrc1[2 * s_n];
        }
        // sweep current chunk
        int cnt = min(32, end - i);
        #pragma unroll 4
        for (int j = 0; j < cnt; j += 2) {
            int jj = j + hh;
            unsigned offB = soff[warp][jj];
            float eh = se[warp][ehsel][jj];
            __half2 hv = *(const __half2*)(hbase + offB);
            float2 fv = __half22float2(hv);
            acc.x += eh * fv.x;
            acc.y += eh * fv.y;
        }
        __syncwarp();
        s = s_n; l = l_n; i = inext;
    }
    acc.x += __shfl_xor_sync(0xffffffffu, acc.x, 16);
    acc.y += __shfl_xor_sync(0xffffffffu, acc.y, 16);
    #pragma unroll
    for (int o = 16; o >= 1; o >>= 1) {
        evs0 += __shfl_xor_sync(0xffffffffu, evs0, o);
        evs1 += __shfl_xor_sync(0xffffffffu, evs1, o);
    }
    float evs = (ehsel == 0) ? evs0 : evs1;
    float inv = 1.f / (evs + 1e-16f);
    float r0 = fmaxf(acc.x * inv + __ldg(&b1[2 * lh]), 0.f);
    float r1 = fmaxf(acc.y * inv + __ldg(&b1[2 * lh + 1]), 0.f);
    float s2 = r0 * g_was[2 * lh] + r1 * g_was[2 * lh + 1];
    float d2 = r0 * g_wad[2 * lh] + r1 * g_wad[2 * lh + 1];
    #pragma unroll
    for (int o = 8; o >= 1; o >>= 1) {
        s2 += __shfl_xor_sync(0xffffffffu, s2, o);
        d2 += __shfl_xor_sync(0xffffffffu, d2, o);
    }
    if (lane == 0) { g_asrc2[n] = s2; g_adst2[n] = d2; }
    if (lane < 16) {
        __half2 rp = __floats2half2_rn(r0, r1);
        *(__half2*)&g_rh[n * HC1 + 2 * lh] = rp;
    }
}

// ---------------------------------------------------------------------------
// K4: layer-2 aggregation of r, software-pipelined like k2 (single head).
// ---------------------------------------------------------------------------
__global__ __launch_bounds__(256) void k4_gather(int N) {
    __shared__ unsigned soff[8][32];
    __shared__ float se[8][32];
    int warp = threadIdx.x >> 5, lane = threadIdx.x & 31;
    int n = blockIdx.x * 8 + warp;
    if (n >= N) return;
    int lh = lane & 15;
    int hh = lane >> 4;
    float adstv = g_adst2[n];
    int start = g_rowstart[n], end = g_rowstart[n + 1];
    float2 acc = make_float2(0.f, 0.f);
    float evs = 0.f;
    const char* hbase = (const char*)g_rh + 4 * lh;

    int i = start;
    int idx0 = i + lane;
    bool v0 = idx0 < end;
    int s = v0 ? g_adj[idx0] : 0;
    float l = v0 ? g_asrc2[s] : -1e30f;

    while (i < end) {
        float a = l + adstv; a = (a > 0.f) ? a : NEG * a;
        float e = __expf(a);
        evs += e;
        soff[warp][lane] = (unsigned)s * (HC1 * 2);
        se[warp][lane] = e;
        __syncwarp();
        int inext = i + 32;
        int s_n = 0;
        float l_n = -1e30f;
        if (inext < end) {
            int idxn = inext + lane;
            bool vn = idxn < end;
            s_n = vn ? g_adj[idxn] : 0;
            if (vn) l_n = g_asrc2[s_n];
        }
        int cnt = min(32, end - i);
        #pragma unroll 4
        for (int j = 0; j < cnt; j += 2) {
            int jj = j + hh;
            unsigned offB = soff[warp][jj];
            float eh = se[warp][jj];
            __half2 hv = *(const __half2*)(hbase + offB);
            float2 fv = __half22float2(hv);
            acc.x += eh * fv.x;
            acc.y += eh * fv.y;
        }
        __syncwarp();
        s = s_n; l = l_n; i = inext;
    }
    acc.x += __shfl_xor_sync(0xffffffffu, acc.x, 16);
    acc.y += __shfl_xor_sync(0xffffffffu, acc.y, 16);
    #pragma unroll
    for (int o = 16; o >= 1; o >>= 1) evs += __shfl_xor_sync(0xffffffffu, evs, o);
    if (lane < 16) {
        float inv = 1.f / (evs + 1e-16f);
        *(float2*)&g_agg[n * HC1 + 2 * lh] = make_float2(acc.x * inv, acc.y * inv);
    }
}

// ---------------------------------------------------------------------------
// K5: out = log_softmax(agg @ W2 + b2). One thread per node, smem staging.
// ---------------------------------------------------------------------------
__global__ __launch_bounds__(256) void k5_out(
    const float* __restrict__ W2, const float* __restrict__ b2,
    float* __restrict__ out, int N) {
    __shared__ float w2s[HC1 * C2];
    __shared__ float b2s[C2];
    __shared__ float hs[256 * 33];
    int tid = threadIdx.x;
    int node0 = blockIdx.x * 256;
    for (int i = tid; i < HC1 * C2; i += 256) w2s[i] = W2[i];
    if (tid < C2) b2s[tid] = b2[tid];

    int nmax = N - node0; if (nmax > 256) nmax = 256;
    for (int i = tid; i < 256 * 32; i += 256) {
        int nn = i >> 5, cc = i & 31;
        hs[nn * 33 + cc] = (nn < nmax) ? g_agg[(node0 + nn) * HC1 + cc] : 0.f;
    }
    __syncthreads();

    if (tid >= nmax) return;
    int n = node0 + tid;
    float acc[C2];
    #pragma unroll
    for (int c = 0; c < C2; c++) acc[c] = 0.f;
    #pragma unroll
    for (int k = 0; k < HC1; k++) {
        float rv = hs[tid * 33 + k];
        #pragma unroll
        for (int c = 0; c < C2; c++) acc[c] += rv * w2s[k * C2 + c];
    }
    float m = -INFINITY;
    #pragma unroll
    for (int c = 0; c < C2; c++) {
        acc[c] += b2s[c];
        m = fmaxf(m, acc[c]);
    }
    float ssum = 0.f;
    #pragma unroll
    for (int c = 0; c < C2; c++) ssum += __expf(acc[c] - m);
    float lse = m + __logf(ssum);
    #pragma unroll
    for (int c = 0; c < C2; c += 4) {
        *(float4*)&out[n * C2 + c] = make_float4(acc[c] - lse, acc[c + 1] - lse,
                                                 acc[c + 2] - lse, acc[c + 3] - lse);
    }
}

// ---------------------------------------------------------------------------
extern "C" void kernel_launch(void* const* d_in, const int* in_sizes, int n_in,
                              void* d_out, int out_size) {
    const float* x   = (const float*)d_in[0];
    const int*   ei  = (const int*)d_in[1];
    const float* W1  = (const float*)d_in[2];
    const float* as1 = (const float*)d_in[3];
    const float* ad1 = (const float*)d_in[4];
    const float* b1  = (const float*)d_in[5];
    const float* W2  = (const float*)d_in[6];
    const float* as2 = (const float*)d_in[7];
    const float* ad2 = (const float*)d_in[8];
    const float* b2  = (const float*)d_in[9];
    float* out = (float*)d_out;

    int N  = in_sizes[0] / FIN;
    int E  = in_sizes[1] / 2;
    int vec = ((E & 3) == 0) ? 1 : 0;
    int eThreads = (E + 3) / 4;
    int scanBlocks = (N + 1023) / 1024;   // <= 128

    static cudaStream_t sB = nullptr;
    static cudaEvent_t evF = nullptr, evJ = nullptr;
    if (sB == nullptr) {
        cudaStreamCreateWithFlags(&sB, cudaStreamNonBlocking);
        cudaEventCreateWithFlags(&evF, cudaEventDisableTiming);
        cudaEventCreateWithFlags(&evJ, cudaEventDisableTiming);
    }

    // Fork: CSR build + watt on sB alongside k1 GEMM on the main stream.
    cudaEventRecord(evF, 0);
    cudaStreamWaitEvent(sB, evF, 0);

    k_hist<<<(eThreads + 255) / 256, 256, 0, sB>>>(ei, E, vec);
    k_scan1<<<scanBlocks, 1024, 0, sB>>>(N);
    k_fill<<<(eThreads + 255) / 256, 256, 0, sB>>>(ei, E, vec);
    k1_gemm<<<(N + 127) / 128, 256>>>(x, W1, as1, ad1, N);    // main stream (4th launch)
    k_watt<<<1, 32, 0, sB>>>(W2, as2, ad2);

    // Join.
    cudaEventRecord(evJ, sB);
    cudaStreamWaitEvent(0, evJ, 0);

    k2_gather<<<(N + 7) / 8, 256>>>(b1, N);
    k4_gather<<<(N + 7) / 8, 256>>>(N);
    k5_out<<<(N + 255) / 256, 256>>>(W2, b2, out, N);
}